// round 14
// baseline (speedup 1.0000x reference)
#include <cuda_runtime.h>

#define N_NODES 50000
#define HID     64
#define NE      800000
#define NPRED   100000
#define NL      2
#define BN_EPS  1e-5f

// ---------------- zeroed blob (single memsetAsync per call) ------------------
#define ZB_INTS  (N_NODES + 512 + 256)
__device__ __align__(256) int g_zb[ZB_INTS];

#define P_CNT   (g_zb)
#define P_DESC  ((volatile unsigned long long*)(g_zb + N_NODES))
#define P_SUMS  ((float*)(g_zb + N_NODES + 512))   // [layer*128 + c]=sum, +64=sumsq

// ---------------- other scratch ----------------------------------------------
__device__ float g_dis[N_NODES];
__device__ float g_x  [N_NODES * HID];
__device__ float g_agg[N_NODES * HID];
__device__ int   g_fill[N_NODES];         // initialized to g_off by k_scan
__device__ int   g_off [N_NODES + 1];
// padded CSR: each node's list padded to multiple of 16 with (0, 0.0f) entries
#define NPAIR (NE + 16 * N_NODES)
__device__ int2  g_pair[NPAIR];           // (src, __float_as_int(norm))

// ---------------- f32x2 helper -----------------------------------------------
__device__ __forceinline__ void ffma2(unsigned long long& d,
                                      unsigned long long a, unsigned long long b) {
    asm("fma.rn.f32x2 %0, %1, %2, %0;" : "+l"(d) : "l"(a), "l"(b));
}
__device__ __forceinline__ unsigned long long pack2(float v) {
    unsigned long long r;
    asm("mov.b64 %0, {%1, %1};" : "=l"(r) : "f"(v));
    return r;
}

// ---------------- degree count (1 edge/thread, max occupancy) ----------------
__global__ void k_count(const int* __restrict__ col) {
    int e = blockIdx.x * 256 + threadIdx.x;
    if (e < NE) atomicAdd(&P_CNT[col[e]], 1);
}

// ------- scan over PADDED counts (decoupled lookback) + pad + fill-init ------
__global__ void k_scan() {
    __shared__ int s[256];
    __shared__ int s_prefix;
    int tid = threadIdx.x, b = blockIdx.x;
    int i = b * 256 + tid;
    int v  = (i < N_NODES) ? P_CNT[i] : 0;
    int vp = (v + 15) & ~15;                      // padded count
    s[tid] = vp; __syncthreads();
    #pragma unroll
    for (int d = 1; d < 256; d <<= 1) {
        int t = (tid >= d) ? s[tid - d] : 0;
        __syncthreads(); s[tid] += t; __syncthreads();
    }
    if (tid == 0) {
        int total = s[255];
        if (b == 0) {
            P_DESC[0] = (2ull << 32) | (unsigned)total;
            s_prefix = 0;
        } else {
            P_DESC[b] = (1ull << 32) | (unsigned)total;
            int pre = 0;
            for (int j = b - 1; j >= 0; ) {
                unsigned long long w;
                do { w = P_DESC[j]; } while ((w >> 32) == 0ull);
                pre += (int)(unsigned)w;
                if ((w >> 32) == 2ull) break;
                j--;
            }
            P_DESC[b] = (2ull << 32) | (unsigned)(pre + total);
            s_prefix = pre;
        }
    }
    __syncthreads();
    if (i < N_NODES) {
        int off = s_prefix + s[tid] - vp;
        g_off[i]  = off;
        g_fill[i] = off;                          // direct-slot base for k_fill
        g_dis[i]  = rsqrtf((float)v + 1.0f);      // +1 self-loop (real degree)
        // write zero-weight pad entries (replaces 25.6 MB memset)
        for (int j = v; j < vp; j++) g_pair[off + j] = make_int2(0, 0);
        if (i == N_NODES - 1) g_off[N_NODES] = s_prefix + s[tid];
    }
}

// ---------------- CSR fill: atomic returns the slot directly -----------------
__global__ void k_fill(const int* __restrict__ row, const int* __restrict__ col) {
    int e = blockIdx.x * 256 + threadIdx.x;
    if (e >= NE) return;
    int r = row[e], c = col[e];
    int p = atomicAdd(&g_fill[c], 1);             // p IS the g_pair slot
    float w = g_dis[r] * g_dis[c];
    g_pair[p] = make_int2(r, __float_as_int(w));
}

// ---------------- input projection: x = [id|n2v] @ Wp + bp -------------------
// Block 256 = 32 row-quads x 8 col-octs. Thread: 4 rows x 8 cols.
#define SWR   514               // u64 per W col-group region (128*4 + 2 skew)
#define PROJ_SMEM (8 * SWR * 8)                   // 32896 B
__global__ __launch_bounds__(256) void k_proj(const float* __restrict__ id_emb,
                                              const float* __restrict__ n2v,
                                              const float* __restrict__ W,  // [128,64]
                                              const float* __restrict__ b) {
    extern __shared__ char smem[];
    unsigned long long* sWd = (unsigned long long*)smem;   // 8 regions x SWR u64
    int tid = threadIdx.x;

    const ulonglong2* Wu2 = (const ulonglong2*)W;   // [128*16]
    for (int i = tid; i < 2048; i += 256) {
        int k = i >> 4, h = i & 15;
        int g = h >> 1, j = (h & 1) * 2;
        ulonglong2 v = Wu2[i];
        *(ulonglong2*)(sWd + g * SWR + k * 4 + j) = v;
    }
    __syncthreads();

    int quad = tid >> 3;
    int oct  = tid & 7;
    int r0 = blockIdx.x * 128 + quad * 4;
    if (r0 >= N_NODES) return;
    int rr[4];
    #pragma unroll
    for (int r = 0; r < 4; r++) {
        int rw = r0 + r;
        rr[r] = (rw < N_NODES) ? rw : (N_NODES - 1);
    }

    unsigned long long acc[4][4];
    const unsigned long long* b2 = (const unsigned long long*)b;
    #pragma unroll
    for (int r = 0; r < 4; r++)
        #pragma unroll
        for (int j = 0; j < 4; j++) acc[r][j] = b2[oct * 4 + j];

    const unsigned long long* sWg = sWd + oct * SWR;

    #pragma unroll
    for (int half = 0; half < 2; half++) {
        const float* src = half ? n2v : id_emb;
        #pragma unroll 4
        for (int k4 = 0; k4 < 16; k4++) {
            float4 xv[4];
            #pragma unroll
            for (int r = 0; r < 4; r++)
                xv[r] = ((const float4*)(src + (size_t)rr[r] * 64))[k4];
            #pragma unroll
            for (int j = 0; j < 4; j++) {
                int k = half * 64 + k4 * 4 + j;
                ulonglong2 wA = *(const ulonglong2*)(sWg + k * 4);
                ulonglong2 wB = *(const ulonglong2*)(sWg + k * 4 + 2);
                #pragma unroll
                for (int r = 0; r < 4; r++) {
                    float xs = (j == 0) ? xv[r].x : (j == 1) ? xv[r].y
                             : (j == 2) ? xv[r].z : xv[r].w;
                    unsigned long long xp = pack2(xs);
                    ffma2(acc[r][0], xp, wA.x);
                    ffma2(acc[r][1], xp, wA.y);
                    ffma2(acc[r][2], xp, wB.x);
                    ffma2(acc[r][3], xp, wB.y);
                }
            }
        }
    }
    #pragma unroll
    for (int r = 0; r < 4; r++) {
        int rw = r0 + r;
        if (rw < N_NODES) {
            ulonglong2* o = (ulonglong2*)(g_x + (size_t)rw * 64 + oct * 8);
            ulonglong2 o0; o0.x = acc[r][0]; o0.y = acc[r][1];
            ulonglong2 o1; o1.x = acc[r][2]; o1.y = acc[r][3];
            o[0] = o0; o[1] = o1;
        }
    }
}

// ---------------- fused gather(x) + GEMM + BN stats --------------------------
// Gather broadcast via uniform LDG (no shfl): all 16 lanes read g_pair[t+k].
#define SXDP 66   // u64 row stride for sXd (64 + 2 pad)
__global__ __launch_bounds__(256) void k_gg(const float* __restrict__ W,     // [64,64]
                                            const float* __restrict__ convb,
                                            int layer) {
    __shared__ float sWs[64 * 64];                 // 16 KB
    __shared__ unsigned long long sXd[16 * SXDP];  // 8.25 KB, (x,x) pairs
    __shared__ float ss[8][64], sg[8][64];         // 4 KB
    int tid = threadIdx.x;
    for (int i = tid; i < 1024; i += 256) ((float4*)sWs)[i] = ((const float4*)W)[i];

    int ln   = tid >> 4;                  // local node 0..15
    int l16  = tid & 15;                  // gather lane
    int node = blockIdx.x * 16 + ln;

    // ---- gather: acc = d^2 * x[node] + sum_e w_e * x[src_e] ----
    float d  = g_dis[node];
    float d2 = d * d;
    float4 xs = ((const float4*)g_x)[node * 16 + l16];
    float4 acc = make_float4(xs.x * d2, xs.y * d2, xs.z * d2, xs.w * d2);

    int beg = g_off[node], end = g_off[node + 1];   // padded: multiple of 16
    for (int t = beg; t < end; t += 16) {
        #pragma unroll
        for (int k = 0; k < 16; k++) {
            int2  pr = __ldg(&g_pair[t + k]);       // uniform within lane group
            float w  = __int_as_float(pr.y);
            float4 v = ((const float4*)g_x)[pr.x * 16 + l16];
            acc.x += w * v.x; acc.y += w * v.y;
            acc.z += w * v.z; acc.w += w * v.w;
        }
    }
    {
        float4* dst = (float4*)(sXd + ln * SXDP + l16 * 4);
        dst[0] = make_float4(acc.x, acc.x, acc.y, acc.y);
        dst[1] = make_float4(acc.z, acc.z, acc.w, acc.w);
    }
    __syncthreads();

    // ---- GEMM: 2 nodes per warp, lane l owns cols (2l, 2l+1) ----
    int w = tid >> 5, l = tid & 31;
    int n0 = blockIdx.x * 16 + 2 * w;
    const unsigned long long* xd0 = sXd + (2 * w)     * SXDP;
    const unsigned long long* xd1 = sXd + (2 * w + 1) * SXDP;
    unsigned long long a0 = 0ull, a1 = 0ull;
    #pragma unroll 8
    for (int k = 0; k < 64; k++) {
        unsigned long long wp = *(const unsigned long long*)(sWs + k * 64 + 2 * l);
        ffma2(a0, xd0[k], wp);
        ffma2(a1, xd1[k], wp);
    }
    float2 cb = *(const float2*)(convb + 2 * l);
    float2 f0, f1;
    asm("mov.b64 {%0, %1}, %2;" : "=f"(f0.x), "=f"(f0.y) : "l"(a0));
    asm("mov.b64 {%0, %1}, %2;" : "=f"(f1.x), "=f"(f1.y) : "l"(a1));
    f0.x += cb.x; f0.y += cb.y;
    f1.x += cb.x; f1.y += cb.y;
    ((float2*)g_agg)[n0 * 32 + l]       = f0;
    ((float2*)g_agg)[(n0 + 1) * 32 + l] = f1;

    // ---- BN stats ----
    ss[w][2 * l]     = f0.x + f1.x;
    ss[w][2 * l + 1] = f0.y + f1.y;
    sg[w][2 * l]     = f0.x * f0.x + f1.x * f1.x;
    sg[w][2 * l + 1] = f0.y * f0.y + f1.y * f1.y;
    __syncthreads();
    if (tid < 32) {
        int t = tid & 15;
        float4 S = make_float4(0.f, 0.f, 0.f, 0.f);
        float* arr0 = (tid < 16) ? &ss[0][0] : &sg[0][0];
        #pragma unroll
        for (int ww = 0; ww < 8; ww++) {
            float4 a = ((const float4*)(arr0 + ww * 64))[t];
            S.x += a.x; S.y += a.y; S.z += a.z; S.w += a.w;
        }
        float* base = P_SUMS + layer * 128 + ((tid < 16) ? 0 : 64);
        atomicAdd(((float4*)base) + t, S);
    }
}

// ---------------- x += relu(BN(agg)) (BN params computed in-block) -----------
__global__ __launch_bounds__(256) void k_apply(const float* __restrict__ gamma,
                                               const float* __restrict__ beta,
                                               int layer) {
    __shared__ float smu[64], ssc[64];
    int tid = threadIdx.x;
    if (tid < 64) {
        const float* base = P_SUMS + layer * 128;
        const float inv_n = 1.0f / (float)N_NODES;
        float mu  = base[tid] * inv_n;
        float var = base[64 + tid] * inv_n - mu * mu;
        smu[tid] = mu;
        ssc[tid] = rsqrtf(var + BN_EPS) * gamma[tid];
    }
    __syncthreads();
    int idx = blockIdx.x * 256 + tid;
    int cq  = idx & 15;
    float4 a  = ((const float4*)g_agg)[idx];
    float4 x  = ((float4*)g_x)[idx];
    float4 mu = ((const float4*)smu)[cq];
    float4 sc = ((const float4*)ssc)[cq];
    float4 bt = ((const float4*)beta)[cq];
    x.x += fmaxf((a.x - mu.x) * sc.x + bt.x, 0.0f);
    x.y += fmaxf((a.y - mu.y) * sc.y + bt.y, 0.0f);
    x.z += fmaxf((a.z - mu.z) * sc.z + bt.z, 0.0f);
    x.w += fmaxf((a.w - mu.w) * sc.w + bt.w, 0.0f);
    ((float4*)g_x)[idx] = x;
}

// ---------------- decoder with fused final BN apply --------------------------
__global__ __launch_bounds__(256) void k_decode(const int* __restrict__ pred,
                                                const float* __restrict__ gamma,
                                                const float* __restrict__ beta,
                                                float* __restrict__ out,
                                                int layer) {
    __shared__ float smu[64], ssc[64], sbt[64];
    int tid = threadIdx.x;
    if (tid < 64) {
        const float* base = P_SUMS + layer * 128;
        const float inv_n = 1.0f / (float)N_NODES;
        float mu  = base[tid] * inv_n;
        float var = base[64 + tid] * inv_n - mu * mu;
        smu[tid] = mu;
        ssc[tid] = rsqrtf(var + BN_EPS) * gamma[tid];
        sbt[tid] = beta[tid];
    }
    __syncthreads();
    int gid = blockIdx.x * 256 + tid;
    int p = gid >> 4;
    int l = gid & 15;
    int a = pred[2 * p];
    int b = pred[2 * p + 1];
    float4 mu = ((const float4*)smu)[l];
    float4 sc = ((const float4*)ssc)[l];
    float4 bt = ((const float4*)sbt)[l];

    float4 xa = ((const float4*)g_x)[a * 16 + l];
    float4 ga = ((const float4*)g_agg)[a * 16 + l];
    float4 za = make_float4(
        xa.x + fmaxf((ga.x - mu.x) * sc.x + bt.x, 0.0f),
        xa.y + fmaxf((ga.y - mu.y) * sc.y + bt.y, 0.0f),
        xa.z + fmaxf((ga.z - mu.z) * sc.z + bt.z, 0.0f),
        xa.w + fmaxf((ga.w - mu.w) * sc.w + bt.w, 0.0f));
    float4 xb = ((const float4*)g_x)[b * 16 + l];
    float4 gb = ((const float4*)g_agg)[b * 16 + l];
    float4 zb = make_float4(
        xb.x + fmaxf((gb.x - mu.x) * sc.x + bt.x, 0.0f),
        xb.y + fmaxf((gb.y - mu.y) * sc.y + bt.y, 0.0f),
        xb.z + fmaxf((gb.z - mu.z) * sc.z + bt.z, 0.0f),
        xb.w + fmaxf((gb.w - mu.w) * sc.w + bt.w, 0.0f));

    float s = za.x * zb.x + za.y * zb.y + za.z * zb.z + za.w * zb.w;
    s += __shfl_xor_sync(0xffffffffu, s, 8);
    s += __shfl_xor_sync(0xffffffffu, s, 4);
    s += __shfl_xor_sync(0xffffffffu, s, 2);
    s += __shfl_xor_sync(0xffffffffu, s, 1);
    if (l == 0) out[p] = s;
}

// ---------------- launch ------------------------------------------------------
extern "C" void kernel_launch(void* const* d_in, const int* in_sizes, int n_in,
                              void* d_out, int out_size) {
    const int*   edge    = (const int*)  d_in[0];
    const int*   pred    = (const int*)  d_in[1];
    const float* id_emb  = (const float*)d_in[2];
    const float* n2v     = (const float*)d_in[3];
    const float* proj_w  = (const float*)d_in[4];
    const float* proj_b  = (const float*)d_in[5];
    const float* conv_w  = (const float*)d_in[6];
    const float* conv_b  = (const float*)d_in[7];
    const float* gamma   = (const float*)d_in[8];
    const float* beta    = (const float*)d_in[9];
    float* out = (float*)d_out;

    static cudaStream_t s2 = nullptr;
    static cudaEvent_t  ev_fork = nullptr, ev_proj = nullptr;
    static int s_init = 0;
    if (!s_init) {
        cudaFuncSetAttribute(k_proj, cudaFuncAttributeMaxDynamicSharedMemorySize,
                             PROJ_SMEM);
        cudaStreamCreateWithFlags(&s2, cudaStreamNonBlocking);
        cudaEventCreateWithFlags(&ev_fork, cudaEventDisableTiming);
        cudaEventCreateWithFlags(&ev_proj, cudaEventDisableTiming);
        s_init = 1;
    }

    // ---- fork: k_proj (writes g_x only) runs concurrently with CSR build ----
    cudaEventRecord(ev_fork, 0);
    cudaStreamWaitEvent(s2, ev_fork, 0);
    k_proj<<<(N_NODES + 127) / 128, 256, PROJ_SMEM, s2>>>(id_emb, n2v, proj_w, proj_b);
    cudaEventRecord(ev_proj, s2);

    // ---- main stream: CSR build ----
    void* zp = nullptr;
    cudaGetSymbolAddress(&zp, g_zb);
    cudaMemsetAsync(zp, 0, ZB_INTS * sizeof(int));

    const int NB_E = (NE + 255) / 256;        // 3125
    const int NB_S = (N_NODES + 255) / 256;   // 196
    k_count<<<NB_E, 256>>>(edge + NE);
    k_scan <<<NB_S, 256>>>();
    k_fill <<<NB_E, 256>>>(edge, edge + NE);

    // ---- join ----
    cudaStreamWaitEvent(0, ev_proj, 0);

    k_gg    <<<N_NODES / 16, 256>>>(conv_w,             conv_b,       0);
    k_apply <<<N_NODES * 16 / 256, 256>>>(gamma,        beta,         0);
    k_gg    <<<N_NODES / 16, 256>>>(conv_w + HID * HID, conv_b + HID, 1);
    k_decode<<<NPRED * 16 / 256, 256>>>(pred, gamma + HID, beta + HID, out, 1);
}

// round 17
// speedup vs baseline: 1.0623x; 1.0623x over previous
#include <cuda_runtime.h>

#define N_NODES 50000
#define HID     64
#define NE      800000
#define NPRED   100000
#define NL      2
#define BN_EPS  1e-5f

// ---------------- zeroed blob (single memsetAsync per call) ------------------
#define ZB_INTS  (N_NODES + 512 + 256)
__device__ __align__(256) int g_zb[ZB_INTS];

#define P_CNT   (g_zb)
#define P_DESC  ((volatile unsigned long long*)(g_zb + N_NODES))
#define P_SUMS  ((float*)(g_zb + N_NODES + 512))   // [layer*128 + c]=sum, +64=sumsq

// ---------------- other scratch ----------------------------------------------
__device__ float g_dis[N_NODES];
__device__ float g_x  [N_NODES * HID];
__device__ float g_agg[N_NODES * HID];
__device__ int   g_fill[N_NODES];         // initialized to g_off by k_scan
__device__ int   g_off [N_NODES + 1];
// padded CSR: each node's list padded to multiple of 16 with (0, 0.0f) entries
#define NPAIR (NE + 16 * N_NODES)
__device__ int2  g_pair[NPAIR];           // (src, __float_as_int(norm))

// ---------------- f32x2 helper -----------------------------------------------
__device__ __forceinline__ void ffma2(unsigned long long& d,
                                      unsigned long long a, unsigned long long b) {
    asm("fma.rn.f32x2 %0, %1, %2, %0;" : "+l"(d) : "l"(a), "l"(b));
}
__device__ __forceinline__ unsigned long long pack2(float v) {
    unsigned long long r;
    asm("mov.b64 %0, {%1, %1};" : "=l"(r) : "f"(v));
    return r;
}

// ---------------- degree count (1 edge/thread, max occupancy) ----------------
__global__ void k_count(const int* __restrict__ col) {
    int e = blockIdx.x * 256 + threadIdx.x;
    if (e < NE) atomicAdd(&P_CNT[col[e]], 1);
}

// ------- scan over PADDED counts (decoupled lookback) + pad + fill-init ------
__global__ void k_scan() {
    __shared__ int s[256];
    __shared__ int s_prefix;
    int tid = threadIdx.x, b = blockIdx.x;
    int i = b * 256 + tid;
    int v  = (i < N_NODES) ? P_CNT[i] : 0;
    int vp = (v + 15) & ~15;                      // padded count
    s[tid] = vp; __syncthreads();
    #pragma unroll
    for (int d = 1; d < 256; d <<= 1) {
        int t = (tid >= d) ? s[tid - d] : 0;
        __syncthreads(); s[tid] += t; __syncthreads();
    }
    if (tid == 0) {
        int total = s[255];
        if (b == 0) {
            P_DESC[0] = (2ull << 32) | (unsigned)total;
            s_prefix = 0;
        } else {
            P_DESC[b] = (1ull << 32) | (unsigned)total;
            int pre = 0;
            for (int j = b - 1; j >= 0; ) {
                unsigned long long w;
                do { w = P_DESC[j]; } while ((w >> 32) == 0ull);
                pre += (int)(unsigned)w;
                if ((w >> 32) == 2ull) break;
                j--;
            }
            P_DESC[b] = (2ull << 32) | (unsigned)(pre + total);
            s_prefix = pre;
        }
    }
    __syncthreads();
    if (i < N_NODES) {
        int off = s_prefix + s[tid] - vp;
        g_off[i]  = off;
        g_fill[i] = off;                          // direct-slot base for k_fill
        g_dis[i]  = rsqrtf((float)v + 1.0f);      // +1 self-loop (real degree)
        // write zero-weight pad entries (replaces 25.6 MB memset)
        for (int j = v; j < vp; j++) g_pair[off + j] = make_int2(0, 0);
        if (i == N_NODES - 1) g_off[N_NODES] = s_prefix + s[tid];
    }
}

// ---------------- CSR fill: atomic returns the slot directly -----------------
__global__ void k_fill(const int* __restrict__ row, const int* __restrict__ col) {
    int e = blockIdx.x * 256 + threadIdx.x;
    if (e >= NE) return;
    int r = row[e], c = col[e];
    int p = atomicAdd(&g_fill[c], 1);             // p IS the g_pair slot
    float w = g_dis[r] * g_dis[c];
    g_pair[p] = make_int2(r, __float_as_int(w));
}

// ---------------- input projection: x = [id|n2v] @ Wp + bp -------------------
// Block 256 = 32 row-quads x 8 col-octs. Thread: 4 rows x 8 cols.
#define SWR   514               // u64 per W col-group region (128*4 + 2 skew)
#define PROJ_SMEM (8 * SWR * 8)                   // 32896 B
__global__ __launch_bounds__(256) void k_proj(const float* __restrict__ id_emb,
                                              const float* __restrict__ n2v,
                                              const float* __restrict__ W,  // [128,64]
                                              const float* __restrict__ b) {
    extern __shared__ char smem[];
    unsigned long long* sWd = (unsigned long long*)smem;   // 8 regions x SWR u64
    int tid = threadIdx.x;

    const ulonglong2* Wu2 = (const ulonglong2*)W;   // [128*16]
    for (int i = tid; i < 2048; i += 256) {
        int k = i >> 4, h = i & 15;
        int g = h >> 1, j = (h & 1) * 2;
        ulonglong2 v = Wu2[i];
        *(ulonglong2*)(sWd + g * SWR + k * 4 + j) = v;
    }
    __syncthreads();

    int quad = tid >> 3;
    int oct  = tid & 7;
    int r0 = blockIdx.x * 128 + quad * 4;
    if (r0 >= N_NODES) return;
    int rr[4];
    #pragma unroll
    for (int r = 0; r < 4; r++) {
        int rw = r0 + r;
        rr[r] = (rw < N_NODES) ? rw : (N_NODES - 1);
    }

    unsigned long long acc[4][4];
    const unsigned long long* b2 = (const unsigned long long*)b;
    #pragma unroll
    for (int r = 0; r < 4; r++)
        #pragma unroll
        for (int j = 0; j < 4; j++) acc[r][j] = b2[oct * 4 + j];

    const unsigned long long* sWg = sWd + oct * SWR;

    #pragma unroll
    for (int half = 0; half < 2; half++) {
        const float* src = half ? n2v : id_emb;
        #pragma unroll 4
        for (int k4 = 0; k4 < 16; k4++) {
            float4 xv[4];
            #pragma unroll
            for (int r = 0; r < 4; r++)
                xv[r] = ((const float4*)(src + (size_t)rr[r] * 64))[k4];
            #pragma unroll
            for (int j = 0; j < 4; j++) {
                int k = half * 64 + k4 * 4 + j;
                ulonglong2 wA = *(const ulonglong2*)(sWg + k * 4);
                ulonglong2 wB = *(const ulonglong2*)(sWg + k * 4 + 2);
                #pragma unroll
                for (int r = 0; r < 4; r++) {
                    float xs = (j == 0) ? xv[r].x : (j == 1) ? xv[r].y
                             : (j == 2) ? xv[r].z : xv[r].w;
                    unsigned long long xp = pack2(xs);
                    ffma2(acc[r][0], xp, wA.x);
                    ffma2(acc[r][1], xp, wA.y);
                    ffma2(acc[r][2], xp, wB.x);
                    ffma2(acc[r][3], xp, wB.y);
                }
            }
        }
    }
    #pragma unroll
    for (int r = 0; r < 4; r++) {
        int rw = r0 + r;
        if (rw < N_NODES) {
            ulonglong2* o = (ulonglong2*)(g_x + (size_t)rw * 64 + oct * 8);
            ulonglong2 o0; o0.x = acc[r][0]; o0.y = acc[r][1];
            ulonglong2 o1; o1.x = acc[r][2]; o1.y = acc[r][3];
            o[0] = o0; o[1] = o1;
        }
    }
}

// ---------------- fused gather(x) + GEMM + BN stats --------------------------
// Gather: shfl-broadcast tiles with double-buffered pair prefetch.
#define SXDP 66   // u64 row stride for sXd (64 + 2 pad)
__global__ __launch_bounds__(256) void k_gg(const float* __restrict__ W,     // [64,64]
                                            const float* __restrict__ convb,
                                            int layer) {
    __shared__ float sWs[64 * 64];                 // 16 KB
    __shared__ unsigned long long sXd[16 * SXDP];  // 8.25 KB, (x,x) pairs
    __shared__ float ss[8][64], sg[8][64];         // 4 KB
    int tid = threadIdx.x;
    for (int i = tid; i < 1024; i += 256) ((float4*)sWs)[i] = ((const float4*)W)[i];

    int ln   = tid >> 4;                  // local node 0..15
    int l16  = tid & 15;                  // gather lane
    int node = blockIdx.x * 16 + ln;
    unsigned m = (tid & 16) ? 0xFFFF0000u : 0x0000FFFFu;

    // ---- gather: acc = d^2 * x[node] + sum_e w_e * x[src_e] ----
    float d  = g_dis[node];
    float d2 = d * d;
    float4 xs = ((const float4*)g_x)[node * 16 + l16];
    float4 acc = make_float4(xs.x * d2, xs.y * d2, xs.z * d2, xs.w * d2);

    int beg = g_off[node], end = g_off[node + 1];   // padded: multiple of 16
    if (beg < end) {
        int2 pr = g_pair[beg + l16];                // prefetch first tile
        for (int t = beg; t < end; ) {
            int2 cur = pr;
            t += 16;
            if (t < end) pr = g_pair[t + l16];      // prefetch next tile early
            #pragma unroll
            for (int k = 0; k < 16; k++) {
                int   r = __shfl_sync(m, cur.x, k, 16);
                float w = __int_as_float(__shfl_sync(m, cur.y, k, 16));
                float4 v = ((const float4*)g_x)[r * 16 + l16];
                acc.x += w * v.x; acc.y += w * v.y;
                acc.z += w * v.z; acc.w += w * v.w;
            }
        }
    }
    {
        float4* dst = (float4*)(sXd + ln * SXDP + l16 * 4);
        dst[0] = make_float4(acc.x, acc.x, acc.y, acc.y);
        dst[1] = make_float4(acc.z, acc.z, acc.w, acc.w);
    }
    __syncthreads();

    // ---- GEMM: 2 nodes per warp, lane l owns cols (2l, 2l+1) ----
    int w = tid >> 5, l = tid & 31;
    int n0 = blockIdx.x * 16 + 2 * w;
    const unsigned long long* xd0 = sXd + (2 * w)     * SXDP;
    const unsigned long long* xd1 = sXd + (2 * w + 1) * SXDP;
    unsigned long long a0 = 0ull, a1 = 0ull;
    #pragma unroll 8
    for (int k = 0; k < 64; k++) {
        unsigned long long wp = *(const unsigned long long*)(sWs + k * 64 + 2 * l);
        ffma2(a0, xd0[k], wp);
        ffma2(a1, xd1[k], wp);
    }
    float2 cb = *(const float2*)(convb + 2 * l);
    float2 f0, f1;
    asm("mov.b64 {%0, %1}, %2;" : "=f"(f0.x), "=f"(f0.y) : "l"(a0));
    asm("mov.b64 {%0, %1}, %2;" : "=f"(f1.x), "=f"(f1.y) : "l"(a1));
    f0.x += cb.x; f0.y += cb.y;
    f1.x += cb.x; f1.y += cb.y;
    ((float2*)g_agg)[n0 * 32 + l]       = f0;
    ((float2*)g_agg)[(n0 + 1) * 32 + l] = f1;

    // ---- BN stats ----
    ss[w][2 * l]     = f0.x + f1.x;
    ss[w][2 * l + 1] = f0.y + f1.y;
    sg[w][2 * l]     = f0.x * f0.x + f1.x * f1.x;
    sg[w][2 * l + 1] = f0.y * f0.y + f1.y * f1.y;
    __syncthreads();
    if (tid < 32) {
        int t = tid & 15;
        float4 S = make_float4(0.f, 0.f, 0.f, 0.f);
        float* arr0 = (tid < 16) ? &ss[0][0] : &sg[0][0];
        #pragma unroll
        for (int ww = 0; ww < 8; ww++) {
            float4 a = ((const float4*)(arr0 + ww * 64))[t];
            S.x += a.x; S.y += a.y; S.z += a.z; S.w += a.w;
        }
        float* base = P_SUMS + layer * 128 + ((tid < 16) ? 0 : 64);
        atomicAdd(((float4*)base) + t, S);
    }
}

// ---------------- x += relu(BN(agg)) (BN params computed in-block) -----------
__global__ __launch_bounds__(256) void k_apply(const float* __restrict__ gamma,
                                               const float* __restrict__ beta,
                                               int layer) {
    __shared__ float smu[64], ssc[64];
    int tid = threadIdx.x;
    if (tid < 64) {
        const float* base = P_SUMS + layer * 128;
        const float inv_n = 1.0f / (float)N_NODES;
        float mu  = base[tid] * inv_n;
        float var = base[64 + tid] * inv_n - mu * mu;
        smu[tid] = mu;
        ssc[tid] = rsqrtf(var + BN_EPS) * gamma[tid];
    }
    __syncthreads();
    int idx = blockIdx.x * 256 + tid;
    int cq  = idx & 15;
    float4 a  = ((const float4*)g_agg)[idx];
    float4 x  = ((float4*)g_x)[idx];
    float4 mu = ((const float4*)smu)[cq];
    float4 sc = ((const float4*)ssc)[cq];
    float4 bt = ((const float4*)beta)[cq];
    x.x += fmaxf((a.x - mu.x) * sc.x + bt.x, 0.0f);
    x.y += fmaxf((a.y - mu.y) * sc.y + bt.y, 0.0f);
    x.z += fmaxf((a.z - mu.z) * sc.z + bt.z, 0.0f);
    x.w += fmaxf((a.w - mu.w) * sc.w + bt.w, 0.0f);
    ((float4*)g_x)[idx] = x;
}

// ---------------- decoder with fused final BN apply --------------------------
__global__ __launch_bounds__(256) void k_decode(const int* __restrict__ pred,
                                                const float* __restrict__ gamma,
                                                const float* __restrict__ beta,
                                                float* __restrict__ out,
                                                int layer) {
    __shared__ float smu[64], ssc[64], sbt[64];
    int tid = threadIdx.x;
    if (tid < 64) {
        const float* base = P_SUMS + layer * 128;
        const float inv_n = 1.0f / (float)N_NODES;
        float mu  = base[tid] * inv_n;
        float var = base[64 + tid] * inv_n - mu * mu;
        smu[tid] = mu;
        ssc[tid] = rsqrtf(var + BN_EPS) * gamma[tid];
        sbt[tid] = beta[tid];
    }
    __syncthreads();
    int gid = blockIdx.x * 256 + tid;
    int p = gid >> 4;
    int l = gid & 15;
    int a = pred[2 * p];
    int b = pred[2 * p + 1];
    float4 mu = ((const float4*)smu)[l];
    float4 sc = ((const float4*)ssc)[l];
    float4 bt = ((const float4*)sbt)[l];

    float4 xa = ((const float4*)g_x)[a * 16 + l];
    float4 ga = ((const float4*)g_agg)[a * 16 + l];
    float4 za = make_float4(
        xa.x + fmaxf((ga.x - mu.x) * sc.x + bt.x, 0.0f),
        xa.y + fmaxf((ga.y - mu.y) * sc.y + bt.y, 0.0f),
        xa.z + fmaxf((ga.z - mu.z) * sc.z + bt.z, 0.0f),
        xa.w + fmaxf((ga.w - mu.w) * sc.w + bt.w, 0.0f));
    float4 xb = ((const float4*)g_x)[b * 16 + l];
    float4 gb = ((const float4*)g_agg)[b * 16 + l];
    float4 zb = make_float4(
        xb.x + fmaxf((gb.x - mu.x) * sc.x + bt.x, 0.0f),
        xb.y + fmaxf((gb.y - mu.y) * sc.y + bt.y, 0.0f),
        xb.z + fmaxf((gb.z - mu.z) * sc.z + bt.z, 0.0f),
        xb.w + fmaxf((gb.w - mu.w) * sc.w + bt.w, 0.0f));

    float s = za.x * zb.x + za.y * zb.y + za.z * zb.z + za.w * zb.w;
    s += __shfl_xor_sync(0xffffffffu, s, 8);
    s += __shfl_xor_sync(0xffffffffu, s, 4);
    s += __shfl_xor_sync(0xffffffffu, s, 2);
    s += __shfl_xor_sync(0xffffffffu, s, 1);
    if (l == 0) out[p] = s;
}

// ---------------- launch ------------------------------------------------------
extern "C" void kernel_launch(void* const* d_in, const int* in_sizes, int n_in,
                              void* d_out, int out_size) {
    const int*   edge    = (const int*)  d_in[0];
    const int*   pred    = (const int*)  d_in[1];
    const float* id_emb  = (const float*)d_in[2];
    const float* n2v     = (const float*)d_in[3];
    const float* proj_w  = (const float*)d_in[4];
    const float* proj_b  = (const float*)d_in[5];
    const float* conv_w  = (const float*)d_in[6];
    const float* conv_b  = (const float*)d_in[7];
    const float* gamma   = (const float*)d_in[8];
    const float* beta    = (const float*)d_in[9];
    float* out = (float*)d_out;

    static cudaStream_t s2 = nullptr;
    static cudaEvent_t  ev_fork = nullptr, ev_proj = nullptr;
    static int s_init = 0;
    if (!s_init) {
        cudaFuncSetAttribute(k_proj, cudaFuncAttributeMaxDynamicSharedMemorySize,
                             PROJ_SMEM);
        cudaStreamCreateWithFlags(&s2, cudaStreamNonBlocking);
        cudaEventCreateWithFlags(&ev_fork, cudaEventDisableTiming);
        cudaEventCreateWithFlags(&ev_proj, cudaEventDisableTiming);
        s_init = 1;
    }

    // ---- fork: k_proj (writes g_x only) runs concurrently with CSR build ----
    cudaEventRecord(ev_fork, 0);
    cudaStreamWaitEvent(s2, ev_fork, 0);
    k_proj<<<(N_NODES + 127) / 128, 256, PROJ_SMEM, s2>>>(id_emb, n2v, proj_w, proj_b);
    cudaEventRecord(ev_proj, s2);

    // ---- main stream: CSR build ----
    void* zp = nullptr;
    cudaGetSymbolAddress(&zp, g_zb);
    cudaMemsetAsync(zp, 0, ZB_INTS * sizeof(int));

    const int NB_E = (NE + 255) / 256;        // 3125
    const int NB_S = (N_NODES + 255) / 256;   // 196
    k_count<<<NB_E, 256>>>(edge + NE);
    k_scan <<<NB_S, 256>>>();
    k_fill <<<NB_E, 256>>>(edge, edge + NE);

    // ---- join ----
    cudaStreamWaitEvent(0, ev_proj, 0);

    k_gg    <<<N_NODES / 16, 256>>>(conv_w,             conv_b,       0);
    k_apply <<<N_NODES * 16 / 256, 256>>>(gamma,        beta,         0);
    k_gg    <<<N_NODES / 16, 256>>>(conv_w + HID * HID, conv_b + HID, 1);
    k_decode<<<NPRED * 16 / 256, 256>>>(pred, gamma + HID, beta + HID, out, 1);
}